// round 3
// baseline (speedup 1.0000x reference)
#include <cuda_runtime.h>
#include <cuda_bf16.h>

// Problem constants
#define B_  16
#define C_  256
#define H_  64
#define W_  64
#define HR  128
#define WR  128
#define HW  (H_*W_)       // 4096
#define HWR (HR*WR)       // 16384

// Scratch: final sampler pixel coords (ix, iy) per output pixel. 2 MB.
__device__ float2 g_grid[B_ * HR * WR];

// ---------------------------------------------------------------------------
// Kernel A: fused 1x1 conv (256 -> 8) + pixel_shuffle + grid construction.
// One thread per low-res pixel (b,h,w); emits 4 high-res pixel coords.
// ---------------------------------------------------------------------------
__global__ __launch_bounds__(256) void dysample_offset_kernel(
    const float* __restrict__ x,
    const float* __restrict__ weight,   // (8, 256)
    const float* __restrict__ bias)     // (8,)
{
    __shared__ float ws[C_ * 8];        // layout [c][o] for broadcast reads
    int tid = threadIdx.x;
    for (int i = tid; i < C_ * 8; i += 256) {
        int o = i >> 8;       // i / 256
        int c = i & 255;      // i % 256
        ws[c * 8 + o] = weight[o * C_ + c];
    }
    __syncthreads();

    int idx = blockIdx.x * 256 + tid;   // flattened (b,h,w), total 65536
    int w = idx & (W_ - 1);
    int h = (idx >> 6) & (H_ - 1);
    int b = idx >> 12;

    float acc[8];
#pragma unroll
    for (int o = 0; o < 8; o++) acc[o] = __ldg(&bias[o]);

    const float* xp = x + (size_t)b * C_ * HW + h * W_ + w;
#pragma unroll 4
    for (int c = 0; c < C_; c++) {
        float v = __ldg(xp + c * HW);
#pragma unroll
        for (int o = 0; o < 8; o++) acc[o] = fmaf(v, ws[c * 8 + o], acc[o]);
    }

    // linspace(-1, 1, 128) step
    const float step = 2.0f / 127.0f;
#pragma unroll
    for (int i = 0; i < 2; i++) {
#pragma unroll
        for (int j = 0; j < 2; j++) {
            int hr = 2 * h + i;
            int wr = 2 * w + j;
            // NOTE the reference's swapped grid: grid[...,0] (x-coord) = gh + off[co=0]
            float g0 = (-1.0f + step * (float)hr) + acc[i * 2 + j];       // x-coord
            float g1 = (-1.0f + step * (float)wr) + acc[4 + i * 2 + j];   // y-coord
            // align_corners=False unnormalize
            float ix = ((g0 + 1.0f) * (float)W_ - 1.0f) * 0.5f;
            float iy = ((g1 + 1.0f) * (float)H_ - 1.0f) * 0.5f;
            g_grid[(b * HR + hr) * WR + wr] = make_float2(ix, iy);
        }
    }
}

// ---------------------------------------------------------------------------
// Kernel B: bilinear grid_sample, padding_mode='zeros'.
// block = 128 threads (one per wr); grid = (C/CPT, HR, B).
// Each thread does CPT channels: 4 gathers + 1 coalesced store per channel.
// ---------------------------------------------------------------------------
#define CPT 32

__global__ __launch_bounds__(128) void dysample_sample_kernel(
    const float* __restrict__ x,
    float* __restrict__ out)
{
    int wr = threadIdx.x;
    int cg = blockIdx.x;          // channel group, 0..C/CPT-1
    int hr = blockIdx.y;
    int b  = blockIdx.z;

    float2 g = g_grid[(b * HR + hr) * WR + wr];
    float ix0f = floorf(g.x);
    float iy0f = floorf(g.y);
    float wx1 = g.x - ix0f;
    float wy1 = g.y - iy0f;
    float wx0 = 1.0f - wx1;
    float wy0 = 1.0f - wy1;

    int ix0 = (int)ix0f, ix1 = ix0 + 1;
    int iy0 = (int)iy0f, iy1 = iy0 + 1;

    float vx0 = ((unsigned)ix0 < (unsigned)W_) ? 1.0f : 0.0f;
    float vx1 = ((unsigned)ix1 < (unsigned)W_) ? 1.0f : 0.0f;
    float vy0 = ((unsigned)iy0 < (unsigned)H_) ? 1.0f : 0.0f;
    float vy1 = ((unsigned)iy1 < (unsigned)H_) ? 1.0f : 0.0f;

    float w00 = wy0 * wx0 * vy0 * vx0;
    float w01 = wy0 * wx1 * vy0 * vx1;
    float w10 = wy1 * wx0 * vy1 * vx0;
    float w11 = wy1 * wx1 * vy1 * vx1;

    int cx0 = min(max(ix0, 0), W_ - 1);
    int cx1 = min(max(ix1, 0), W_ - 1);
    int cy0 = min(max(iy0, 0), H_ - 1);
    int cy1 = min(max(iy1, 0), H_ - 1);

    int i00 = cy0 * W_ + cx0;
    int i01 = cy0 * W_ + cx1;
    int i10 = cy1 * W_ + cx0;
    int i11 = cy1 * W_ + cx1;

    int c0 = cg * CPT;
    const float* xb = x + (size_t)(b * C_ + c0) * HW;
    float* op = out + ((size_t)(b * C_ + c0) * HR + hr) * WR + wr;

#pragma unroll 4
    for (int c = 0; c < CPT; c++) {
        const float* p = xb + c * HW;
        float v = fmaf(w00, __ldg(p + i00),
                  fmaf(w01, __ldg(p + i01),
                  fmaf(w10, __ldg(p + i10),
                       w11 * __ldg(p + i11))));
        op[(size_t)c * HWR] = v;
    }
}

// ---------------------------------------------------------------------------
extern "C" void kernel_launch(void* const* d_in, const int* in_sizes, int n_in,
                              void* d_out, int out_size)
{
    const float* x      = (const float*)d_in[0];
    const float* weight = (const float*)d_in[1];
    const float* bias   = (const float*)d_in[2];
    float* out          = (float*)d_out;

    // Kernel A: 65536 low-res pixels, 256 threads/block
    dysample_offset_kernel<<<(B_ * H_ * W_) / 256, 256>>>(x, weight, bias);

    // Kernel B
    dim3 grid(C_ / CPT, HR, B_);
    dysample_sample_kernel<<<grid, 128>>>(x, out);
}

// round 4
// speedup vs baseline: 2.0665x; 2.0665x over previous
#include <cuda_runtime.h>
#include <cuda_bf16.h>

// Problem constants
#define B_  16
#define C_  256
#define H_  64
#define W_  64
#define HR  128
#define WR  128
#define HW  (H_*W_)       // 4096
#define HWR (HR*WR)       // 16384

// Scratch buffers (static device globals — no allocation at runtime)
__device__ float2 g_grid[B_ * HR * WR];            // 2 MB: sampler pixel coords
__device__ float  g_xt[(size_t)B_ * HW * C_];      // 64 MB: x in NHWC layout

// ---------------------------------------------------------------------------
// Kernel T: NCHW -> NHWC transpose. Per-b matrix transpose of (C=256)x(HW=4096).
// Tiled 32x32 through smem; both global accesses coalesced.
// ---------------------------------------------------------------------------
__global__ __launch_bounds__(256) void dysample_transpose_kernel(
    const float* __restrict__ x)
{
    __shared__ float tile[32][33];
    int bx = blockIdx.x;          // hw tile: 0..127
    int by = blockIdx.y;          // c  tile: 0..7
    int b  = blockIdx.z;
    int tx = threadIdx.x;         // 0..31
    int ty = threadIdx.y;         // 0..7

    int s = bx * 32 + tx;
#pragma unroll
    for (int k = 0; k < 4; k++) {
        int c = by * 32 + ty + k * 8;
        tile[ty + k * 8][tx] = x[((size_t)(b * C_ + c)) * HW + s];
    }
    __syncthreads();

    int c2 = by * 32 + tx;
#pragma unroll
    for (int k = 0; k < 4; k++) {
        int s2 = bx * 32 + ty + k * 8;
        g_xt[((size_t)(b * HW + s2)) * C_ + c2] = tile[tx][ty + k * 8];
    }
}

// ---------------------------------------------------------------------------
// Kernel A: fused 1x1 conv (256 -> 8) + pixel_shuffle + grid construction.
// One thread per low-res pixel (b,h,w); emits 4 high-res pixel coords.
// Weight smem reads vectorized (2x LDS.128 per channel instead of 8x LDS.32).
// ---------------------------------------------------------------------------
__global__ __launch_bounds__(256) void dysample_offset_kernel(
    const float* __restrict__ x,
    const float* __restrict__ weight,   // (8, 256)
    const float* __restrict__ bias)     // (8,)
{
    __shared__ float4 ws4[C_ * 2];      // layout [c][o/4] for vector broadcast
    int tid = threadIdx.x;
    for (int i = tid; i < C_ * 8; i += 256) {
        int o = i >> 8;       // i / 256
        int c = i & 255;      // i % 256
        ((float*)ws4)[c * 8 + o] = weight[o * C_ + c];
    }
    __syncthreads();

    int idx = blockIdx.x * 256 + tid;   // flattened (b,h,w), total 65536
    int w = idx & (W_ - 1);
    int h = (idx >> 6) & (H_ - 1);
    int b = idx >> 12;

    float acc[8];
#pragma unroll
    for (int o = 0; o < 8; o++) acc[o] = __ldg(&bias[o]);

    const float* xp = x + (size_t)b * C_ * HW + h * W_ + w;
#pragma unroll 8
    for (int c = 0; c < C_; c++) {
        float v = __ldg(xp + c * HW);
        float4 wa = ws4[c * 2 + 0];
        float4 wb = ws4[c * 2 + 1];
        acc[0] = fmaf(v, wa.x, acc[0]);
        acc[1] = fmaf(v, wa.y, acc[1]);
        acc[2] = fmaf(v, wa.z, acc[2]);
        acc[3] = fmaf(v, wa.w, acc[3]);
        acc[4] = fmaf(v, wb.x, acc[4]);
        acc[5] = fmaf(v, wb.y, acc[5]);
        acc[6] = fmaf(v, wb.z, acc[6]);
        acc[7] = fmaf(v, wb.w, acc[7]);
    }

    // linspace(-1, 1, 128) step
    const float step = 2.0f / 127.0f;
#pragma unroll
    for (int i = 0; i < 2; i++) {
#pragma unroll
        for (int j = 0; j < 2; j++) {
            int hr = 2 * h + i;
            int wr = 2 * w + j;
            // Reference's swapped grid: grid[...,0] (x-coord) = gh + off[co=0]
            float g0 = (-1.0f + step * (float)hr) + acc[i * 2 + j];       // x-coord
            float g1 = (-1.0f + step * (float)wr) + acc[4 + i * 2 + j];   // y-coord
            // align_corners=False unnormalize
            float ix = ((g0 + 1.0f) * (float)W_ - 1.0f) * 0.5f;
            float iy = ((g1 + 1.0f) * (float)H_ - 1.0f) * 0.5f;
            g_grid[(b * HR + hr) * WR + wr] = make_float2(ix, iy);
        }
    }
}

// ---------------------------------------------------------------------------
// Kernel S: bilinear grid_sample, padding_mode='zeros', reading NHWC g_xt.
// block = 256 threads (8 warps); each block = 32 consecutive output pixels
// (one hr row segment) x all 256 channels. Each warp owns 4 pixels.
// Per pixel: 4 corners, each a contiguous 1KB channel span -> every LDG.32
// is one fully-coalesced 128B line (1 wavefront). Results staged in smem
// [c][px] (conflict-free), then written NCHW-coalesced.
// ---------------------------------------------------------------------------
__global__ __launch_bounds__(256) void dysample_sample_nhwc_kernel(
    float* __restrict__ out)
{
    __shared__ float res_s[C_][33];   // [channel][pixel], pad for phase1 STS

    int wr0 = blockIdx.x * 32;
    int hr  = blockIdx.y;
    int b   = blockIdx.z;
    int tid  = threadIdx.x;
    int lane = tid & 31;
    int wid  = tid >> 5;              // 0..7

    // ---- Phase 1: gather + bilinear blend ----
#pragma unroll
    for (int pp = 0; pp < 4; pp++) {
        int px = wid * 4 + pp;
        int wr = wr0 + px;

        float2 g = g_grid[(b * HR + hr) * WR + wr];
        float ix0f = floorf(g.x);
        float iy0f = floorf(g.y);
        float wx1 = g.x - ix0f;
        float wy1 = g.y - iy0f;
        float wx0 = 1.0f - wx1;
        float wy0 = 1.0f - wy1;

        int ix0 = (int)ix0f, ix1 = ix0 + 1;
        int iy0 = (int)iy0f, iy1 = iy0 + 1;

        float vx0 = ((unsigned)ix0 < (unsigned)W_) ? 1.0f : 0.0f;
        float vx1 = ((unsigned)ix1 < (unsigned)W_) ? 1.0f : 0.0f;
        float vy0 = ((unsigned)iy0 < (unsigned)H_) ? 1.0f : 0.0f;
        float vy1 = ((unsigned)iy1 < (unsigned)H_) ? 1.0f : 0.0f;

        float w00 = wy0 * wx0 * vy0 * vx0;
        float w01 = wy0 * wx1 * vy0 * vx1;
        float w10 = wy1 * wx0 * vy1 * vx0;
        float w11 = wy1 * wx1 * vy1 * vx1;

        int cx0 = min(max(ix0, 0), W_ - 1);
        int cx1 = min(max(ix1, 0), W_ - 1);
        int cy0 = min(max(iy0, 0), H_ - 1);
        int cy1 = min(max(iy1, 0), H_ - 1);

        // NHWC corner base pointers: channel stride 1
        const float* p00 = g_xt + (((size_t)(b * HW + cy0 * W_ + cx0)) << 8);
        const float* p01 = g_xt + (((size_t)(b * HW + cy0 * W_ + cx1)) << 8);
        const float* p10 = g_xt + (((size_t)(b * HW + cy1 * W_ + cx0)) << 8);
        const float* p11 = g_xt + (((size_t)(b * HW + cy1 * W_ + cx1)) << 8);

        float v00[8], v01[8], v10[8], v11[8];
#pragma unroll
        for (int j = 0; j < 8; j++) {
            int c = lane + 32 * j;
            v00[j] = __ldg(p00 + c);
            v01[j] = __ldg(p01 + c);
            v10[j] = __ldg(p10 + c);
            v11[j] = __ldg(p11 + c);
        }
#pragma unroll
        for (int j = 0; j < 8; j++) {
            int c = lane + 32 * j;
            float v = fmaf(w00, v00[j],
                      fmaf(w01, v01[j],
                      fmaf(w10, v10[j],
                           w11 * v11[j])));
            res_s[c][px] = v;   // addr stride per lane = 33 words -> conflict-free
        }
    }
    __syncthreads();

    // ---- Phase 2: coalesced NCHW write-out ----
    int px2 = tid & 31;           // lanes -> consecutive wr
    int cb  = tid >> 5;           // 0..7
    float* op = out + (((size_t)(b * C_) * HR + hr)) * WR + wr0 + px2;
#pragma unroll
    for (int k = 0; k < 32; k++) {
        int c = cb + k * 8;
        op[(size_t)c * HWR] = res_s[c][px2];
    }
}

// ---------------------------------------------------------------------------
extern "C" void kernel_launch(void* const* d_in, const int* in_sizes, int n_in,
                              void* d_out, int out_size)
{
    const float* x      = (const float*)d_in[0];
    const float* weight = (const float*)d_in[1];
    const float* bias   = (const float*)d_in[2];
    float* out          = (float*)d_out;

    // T: NCHW -> NHWC
    {
        dim3 grid(HW / 32, C_ / 32, B_);
        dim3 block(32, 8);
        dysample_transpose_kernel<<<grid, block>>>(x);
    }

    // A: offsets -> sampler coords
    dysample_offset_kernel<<<(B_ * H_ * W_) / 256, 256>>>(x, weight, bias);

    // S: NHWC gather + blend + NCHW write
    {
        dim3 grid(WR / 32, HR, B_);
        dysample_sample_nhwc_kernel<<<grid, 256>>>(out);
    }
}

// round 7
// speedup vs baseline: 2.5001x; 1.2098x over previous
#include <cuda_runtime.h>
#include <cuda_bf16.h>

// Problem constants
#define B_  16
#define C_  256
#define H_  64
#define W_  64
#define HR  128
#define WR  128
#define HW  (H_*W_)       // 4096
#define HWR (HR*WR)       // 16384

// Scratch buffers (static device globals — no allocation at runtime)
__device__ float2 g_grid[B_ * HR * WR];            // 2 MB: sampler pixel coords
__device__ float  g_xt[(size_t)B_ * HW * C_];      // 64 MB: x in NHWC layout

// ---------------------------------------------------------------------------
// Kernel T: NCHW -> NHWC transpose. Per-b matrix transpose of (C=256)x(HW=4096).
// Tiled 32x32 through smem; both global accesses coalesced.
// ---------------------------------------------------------------------------
__global__ __launch_bounds__(256) void dysample_transpose_kernel(
    const float* __restrict__ x)
{
    __shared__ float tile[32][33];
    int bx = blockIdx.x;          // hw tile: 0..127
    int by = blockIdx.y;          // c  tile: 0..7
    int b  = blockIdx.z;
    int tx = threadIdx.x;         // 0..31
    int ty = threadIdx.y;         // 0..7

    int s = bx * 32 + tx;
#pragma unroll
    for (int k = 0; k < 4; k++) {
        int c = by * 32 + ty + k * 8;
        tile[ty + k * 8][tx] = x[((size_t)(b * C_ + c)) * HW + s];
    }
    __syncthreads();

    int c2 = by * 32 + tx;
#pragma unroll
    for (int k = 0; k < 4; k++) {
        int s2 = bx * 32 + ty + k * 8;
        g_xt[((size_t)(b * HW + s2)) * C_ + c2] = tile[tx][ty + k * 8];
    }
}

// ---------------------------------------------------------------------------
// Kernel A2: fused 1x1 conv (256 -> 8) + pixel_shuffle + grid construction,
// reading NHWC g_xt (L2-hot right after T). One WARP per low-res pixel:
// lane handles channels {lane + 32j}, 64 FMA, butterfly-reduce 8 accumulators,
// lanes 0..3 emit the 4 high-res sampler coords.
// ---------------------------------------------------------------------------
__global__ __launch_bounds__(256) void dysample_offset_nhwc_kernel(
    const float* __restrict__ weight,   // (8, 256), [o][c]
    const float* __restrict__ bias)     // (8,)
{
    __shared__ float ws[8 * C_];        // same [o][c] layout: stride-1 LDS
    int tid = threadIdx.x;
    for (int i = tid; i < 8 * C_; i += 256) ws[i] = weight[i];
    __syncthreads();

    int lane = tid & 31;
    int wid  = tid >> 5;
    int p = blockIdx.x * 8 + wid;       // flattened (b,h,w), total 65536
    int w = p & (W_ - 1);
    int h = (p >> 6) & (H_ - 1);
    int b = p >> 12;

    const float* xp = g_xt + (size_t)p * C_;

    float acc[8];
#pragma unroll
    for (int o = 0; o < 8; o++) acc[o] = 0.0f;

#pragma unroll
    for (int j = 0; j < 8; j++) {
        int c = lane + 32 * j;
        float v = __ldg(xp + c);
#pragma unroll
        for (int o = 0; o < 8; o++)
            acc[o] = fmaf(v, ws[o * C_ + c], acc[o]);
    }

    // Butterfly reduce across the warp (all lanes end with full sums)
#pragma unroll
    for (int off = 16; off; off >>= 1) {
#pragma unroll
        for (int o = 0; o < 8; o++)
            acc[o] += __shfl_xor_sync(0xffffffffu, acc[o], off);
    }

    if (lane < 4) {
        int i = lane >> 1;
        int j = lane & 1;
        int hr = 2 * h + i;
        int wr = 2 * w + j;
        const float step = 2.0f / 127.0f;
        float o0 = acc[i * 2 + j]     + __ldg(&bias[i * 2 + j]);
        float o1 = acc[4 + i * 2 + j] + __ldg(&bias[4 + i * 2 + j]);
        // Reference's swapped grid: grid[...,0] (x-coord) = gh + off[co=0]
        float g0 = (-1.0f + step * (float)hr) + o0;   // x-coord
        float g1 = (-1.0f + step * (float)wr) + o1;   // y-coord
        // align_corners=False unnormalize
        float ix = ((g0 + 1.0f) * (float)W_ - 1.0f) * 0.5f;
        float iy = ((g1 + 1.0f) * (float)H_ - 1.0f) * 0.5f;
        g_grid[(b * HR + hr) * WR + wr] = make_float2(ix, iy);
    }
}

// ---------------------------------------------------------------------------
// Kernel S2: bilinear grid_sample, padding_mode='zeros', reading NHWC g_xt.
// block = 256 threads (8 warps); each block = 32 consecutive output pixels
// x all 256 channels; each warp owns 4 pixels. Corners loaded as float4
// (2x LDG.128 per corner = contiguous 1KB channel span, fully coalesced).
// Results staged in smem with a bit-permuted row index so both the
// vectorized phase-1 stores and the phase-2 reads are conflict-free.
//   row(c) = ((c&3)<<6) | ((c>>7)<<5) | ((c>>2)&31)
// ---------------------------------------------------------------------------
__global__ __launch_bounds__(256) void dysample_sample_nhwc_kernel(
    float* __restrict__ out)
{
    __shared__ float res_s[C_ * 33];   // [row(c)][px], row stride 33

    int wr0 = blockIdx.x * 32;
    int hr  = blockIdx.y;
    int b   = blockIdx.z;
    int tid  = threadIdx.x;
    int lane = tid & 31;
    int wid  = tid >> 5;              // 0..7

    // ---- Phase 1: gather + bilinear blend ----
#pragma unroll
    for (int pp = 0; pp < 4; pp++) {
        int px = wid * 4 + pp;
        int wr = wr0 + px;

        float2 g = g_grid[(b * HR + hr) * WR + wr];
        float ix0f = floorf(g.x);
        float iy0f = floorf(g.y);
        float wx1 = g.x - ix0f;
        float wy1 = g.y - iy0f;
        float wx0 = 1.0f - wx1;
        float wy0 = 1.0f - wy1;

        int ix0 = (int)ix0f, ix1 = ix0 + 1;
        int iy0 = (int)iy0f, iy1 = iy0 + 1;

        float vx0 = ((unsigned)ix0 < (unsigned)W_) ? 1.0f : 0.0f;
        float vx1 = ((unsigned)ix1 < (unsigned)W_) ? 1.0f : 0.0f;
        float vy0 = ((unsigned)iy0 < (unsigned)H_) ? 1.0f : 0.0f;
        float vy1 = ((unsigned)iy1 < (unsigned)H_) ? 1.0f : 0.0f;

        float w00 = wy0 * wx0 * vy0 * vx0;
        float w01 = wy0 * wx1 * vy0 * vx1;
        float w10 = wy1 * wx0 * vy1 * vx0;
        float w11 = wy1 * wx1 * vy1 * vx1;

        int cx0 = min(max(ix0, 0), W_ - 1);
        int cx1 = min(max(ix1, 0), W_ - 1);
        int cy0 = min(max(iy0, 0), H_ - 1);
        int cy1 = min(max(iy1, 0), H_ - 1);

        // NHWC corner base pointers (1KB-aligned)
        const float4* q00 = (const float4*)(g_xt + (((size_t)(b * HW + cy0 * W_ + cx0)) << 8));
        const float4* q01 = (const float4*)(g_xt + (((size_t)(b * HW + cy0 * W_ + cx1)) << 8));
        const float4* q10 = (const float4*)(g_xt + (((size_t)(b * HW + cy1 * W_ + cx0)) << 8));
        const float4* q11 = (const float4*)(g_xt + (((size_t)(b * HW + cy1 * W_ + cx1)) << 8));

        // channels 4*lane..4*lane+3  and  128+4*lane..128+4*lane+3
        float4 a00 = __ldg(q00 + lane);
        float4 a01 = __ldg(q01 + lane);
        float4 a10 = __ldg(q10 + lane);
        float4 a11 = __ldg(q11 + lane);
        float4 b00 = __ldg(q00 + 32 + lane);
        float4 b01 = __ldg(q01 + 32 + lane);
        float4 b10 = __ldg(q10 + 32 + lane);
        float4 b11 = __ldg(q11 + 32 + lane);

        float4 r0, r1;
        r0.x = fmaf(w00, a00.x, fmaf(w01, a01.x, fmaf(w10, a10.x, w11 * a11.x)));
        r0.y = fmaf(w00, a00.y, fmaf(w01, a01.y, fmaf(w10, a10.y, w11 * a11.y)));
        r0.z = fmaf(w00, a00.z, fmaf(w01, a01.z, fmaf(w10, a10.z, w11 * a11.z)));
        r0.w = fmaf(w00, a00.w, fmaf(w01, a01.w, fmaf(w10, a10.w, w11 * a11.w)));
        r1.x = fmaf(w00, b00.x, fmaf(w01, b01.x, fmaf(w10, b10.x, w11 * b11.x)));
        r1.y = fmaf(w00, b00.y, fmaf(w01, b01.y, fmaf(w10, b10.y, w11 * b11.y)));
        r1.z = fmaf(w00, b00.z, fmaf(w01, b01.z, fmaf(w10, b10.z, w11 * b11.z)));
        r1.w = fmaf(w00, b00.w, fmaf(w01, b01.w, fmaf(w10, b10.w, w11 * b11.w)));

        // Permuted-row stores: row = k*64 + m*32 + lane (k = comp, m = half)
        // lane stride in smem words = 33 -> conflict-free
        res_s[(0 * 64 + lane) * 33 + px]      = r0.x;
        res_s[(1 * 64 + lane) * 33 + px]      = r0.y;
        res_s[(2 * 64 + lane) * 33 + px]      = r0.z;
        res_s[(3 * 64 + lane) * 33 + px]      = r0.w;
        res_s[(0 * 64 + 32 + lane) * 33 + px] = r1.x;
        res_s[(1 * 64 + 32 + lane) * 33 + px] = r1.y;
        res_s[(2 * 64 + 32 + lane) * 33 + px] = r1.z;
        res_s[(3 * 64 + 32 + lane) * 33 + px] = r1.w;
    }
    __syncthreads();

    // ---- Phase 2: coalesced NCHW write-out ----
    int px2 = tid & 31;           // lanes -> consecutive wr
    int cb  = tid >> 5;           // 0..7
    float* op = out + (((size_t)(b * C_) * HR + hr)) * WR + wr0 + px2;
#pragma unroll
    for (int k = 0; k < 32; k++) {
        int c = cb + k * 8;
        int row = ((c & 3) << 6) | ((c >> 7) << 5) | ((c >> 2) & 31);
        op[(size_t)c * HWR] = res_s[row * 33 + px2];
    }
}

// ---------------------------------------------------------------------------
extern "C" void kernel_launch(void* const* d_in, const int* in_sizes, int n_in,
                              void* d_out, int out_size)
{
    const float* x      = (const float*)d_in[0];
    const float* weight = (const float*)d_in[1];
    const float* bias   = (const float*)d_in[2];
    float* out          = (float*)d_out;

    // T: NCHW -> NHWC
    {
        dim3 grid(HW / 32, C_ / 32, B_);
        dim3 block(32, 8);
        dysample_transpose_kernel<<<grid, block>>>(x);
    }

    // A2: offsets -> sampler coords (reads NHWC g_xt, L2-hot)
    dysample_offset_nhwc_kernel<<<(B_ * H_ * W_) / 8, 256>>>(weight, bias);

    // S2: NHWC float4 gather + blend + NCHW write
    {
        dim3 grid(WR / 32, HR, B_);
        dysample_sample_nhwc_kernel<<<grid, 256>>>(out);
    }
}

// round 9
// speedup vs baseline: 2.5894x; 1.0357x over previous
#include <cuda_runtime.h>
#include <cuda_fp16.h>
#include <cuda_bf16.h>

// Problem constants
#define B_  16
#define C_  256
#define H_  64
#define W_  64
#define HR  128
#define WR  128
#define HW  (H_*W_)       // 4096
#define HWR (HR*WR)       // 16384

// Scratch buffers (static device globals — no allocation at runtime)
__device__ float2 g_grid[B_ * HR * WR];            // 2 MB: sampler pixel coords
__device__ float  g_xt [(size_t)B_ * HW * C_];     // 64 MB: x NHWC fp32 (offset conv)
__device__ __half g_xth[(size_t)B_ * HW * C_];     // 32 MB: x NHWC fp16 (sampler gathers)

// ---------------------------------------------------------------------------
// Kernel T: NCHW -> NHWC transpose, emitting fp32 + fp16 copies.
// Tiled 32x32 through smem; all global accesses coalesced.
// ---------------------------------------------------------------------------
__global__ __launch_bounds__(256) void dysample_transpose_kernel(
    const float* __restrict__ x)
{
    __shared__ float tile[32][33];
    int bx = blockIdx.x;          // hw tile: 0..127
    int by = blockIdx.y;          // c  tile: 0..7
    int b  = blockIdx.z;
    int tx = threadIdx.x;         // 0..31
    int ty = threadIdx.y;         // 0..7

    int s = bx * 32 + tx;
#pragma unroll
    for (int k = 0; k < 4; k++) {
        int c = by * 32 + ty + k * 8;
        tile[ty + k * 8][tx] = x[((size_t)(b * C_ + c)) * HW + s];
    }
    __syncthreads();

    int c2 = by * 32 + tx;
#pragma unroll
    for (int k = 0; k < 4; k++) {
        int s2 = bx * 32 + ty + k * 8;
        g_xt[((size_t)(b * HW + s2)) * C_ + c2] = tile[tx][ty + k * 8];
    }

    // fp16 NHWC copy: lanes 0..15 each write one half2 (2 adjacent channels).
    // tile reads: banks (2*tx + sl) % 32 distinct over tx=0..15 -> conflict-free.
    if (tx < 16) {
#pragma unroll
        for (int k = 0; k < 4; k++) {
            int sl = ty + k * 8;
            int s2 = bx * 32 + sl;
            float v0 = tile[2 * tx + 0][sl];
            float v1 = tile[2 * tx + 1][sl];
            __half2 h = __floats2half2_rn(v0, v1);
            ((__half2*)(g_xth + ((size_t)(b * HW + s2)) * C_))[by * 16 + tx] = h;
        }
    }
}

// ---------------------------------------------------------------------------
// Kernel A2: fused 1x1 conv (256 -> 8) + pixel_shuffle + grid construction,
// reading NHWC fp32 g_xt (L2-hot right after T). One WARP per low-res pixel.
// Offsets must be fp32-accurate: sample POSITIONS feed the image gradient,
// so fp16 here would blow the error budget (values may be fp16; positions not).
// ---------------------------------------------------------------------------
__global__ __launch_bounds__(256) void dysample_offset_nhwc_kernel(
    const float* __restrict__ weight,   // (8, 256), [o][c]
    const float* __restrict__ bias)     // (8,)
{
    __shared__ float ws[8 * C_];        // same [o][c] layout: stride-1 LDS
    int tid = threadIdx.x;
    for (int i = tid; i < 8 * C_; i += 256) ws[i] = weight[i];
    __syncthreads();

    int lane = tid & 31;
    int wid  = tid >> 5;
    int p = blockIdx.x * 8 + wid;       // flattened (b,h,w), total 65536
    int w = p & (W_ - 1);
    int h = (p >> 6) & (H_ - 1);
    int b = p >> 12;

    const float* xp = g_xt + (size_t)p * C_;

    float acc[8];
#pragma unroll
    for (int o = 0; o < 8; o++) acc[o] = 0.0f;

#pragma unroll
    for (int j = 0; j < 8; j++) {
        int c = lane + 32 * j;
        float v = __ldg(xp + c);
#pragma unroll
        for (int o = 0; o < 8; o++)
            acc[o] = fmaf(v, ws[o * C_ + c], acc[o]);
    }

    // Butterfly reduce across the warp
#pragma unroll
    for (int off = 16; off; off >>= 1) {
#pragma unroll
        for (int o = 0; o < 8; o++)
            acc[o] += __shfl_xor_sync(0xffffffffu, acc[o], off);
    }

    if (lane < 4) {
        int i = lane >> 1;
        int j = lane & 1;
        int hr = 2 * h + i;
        int wr = 2 * w + j;
        const float step = 2.0f / 127.0f;
        float o0 = acc[i * 2 + j]     + __ldg(&bias[i * 2 + j]);
        float o1 = acc[4 + i * 2 + j] + __ldg(&bias[4 + i * 2 + j]);
        // Reference's swapped grid: grid[...,0] (x-coord) = gh + off[co=0]
        float g0 = (-1.0f + step * (float)hr) + o0;   // x-coord
        float g1 = (-1.0f + step * (float)wr) + o1;   // y-coord
        // align_corners=False unnormalize
        float ix = ((g0 + 1.0f) * (float)W_ - 1.0f) * 0.5f;
        float iy = ((g1 + 1.0f) * (float)H_ - 1.0f) * 0.5f;
        g_grid[(b * HR + hr) * WR + wr] = make_float2(ix, iy);
    }
}

// ---------------------------------------------------------------------------
// Kernel S3: bilinear grid_sample, padding_mode='zeros', gathering fp16 NHWC.
// block = 256 threads (8 warps); block = 32 output pixels x all 256 channels;
// each warp owns 4 pixels. One corner = ONE LDG.128 (uint4 = 8 halves/lane
// x 32 lanes = 256 ch, contiguous 512B). Blend in fp32. Smem staging uses
// row(c) = (c&7)*32 + (c>>3): phase-1 stores lane-stride 33 (conflict-free),
// phase-2 reads constant-row stride-1 (conflict-free).
// ---------------------------------------------------------------------------
__global__ __launch_bounds__(256) void dysample_sample_nhwc_kernel(
    float* __restrict__ out)
{
    __shared__ float res_s[C_ * 33];   // [row(c)][px]

    int wr0 = blockIdx.x * 32;
    int hr  = blockIdx.y;
    int b   = blockIdx.z;
    int tid  = threadIdx.x;
    int lane = tid & 31;
    int wid  = tid >> 5;              // 0..7

    // ---- Phase 1: gather + bilinear blend ----
#pragma unroll
    for (int pp = 0; pp < 4; pp++) {
        int px = wid * 4 + pp;
        int wr = wr0 + px;

        float2 g = g_grid[(b * HR + hr) * WR + wr];
        float ix0f = floorf(g.x);
        float iy0f = floorf(g.y);
        float wx1 = g.x - ix0f;
        float wy1 = g.y - iy0f;
        float wx0 = 1.0f - wx1;
        float wy0 = 1.0f - wy1;

        int ix0 = (int)ix0f, ix1 = ix0 + 1;
        int iy0 = (int)iy0f, iy1 = iy0 + 1;

        float vx0 = ((unsigned)ix0 < (unsigned)W_) ? 1.0f : 0.0f;
        float vx1 = ((unsigned)ix1 < (unsigned)W_) ? 1.0f : 0.0f;
        float vy0 = ((unsigned)iy0 < (unsigned)H_) ? 1.0f : 0.0f;
        float vy1 = ((unsigned)iy1 < (unsigned)H_) ? 1.0f : 0.0f;

        float w00 = wy0 * wx0 * vy0 * vx0;
        float w01 = wy0 * wx1 * vy0 * vx1;
        float w10 = wy1 * wx0 * vy1 * vx0;
        float w11 = wy1 * wx1 * vy1 * vx1;

        int cx0 = min(max(ix0, 0), W_ - 1);
        int cx1 = min(max(ix1, 0), W_ - 1);
        int cy0 = min(max(iy0, 0), H_ - 1);
        int cy1 = min(max(iy1, 0), H_ - 1);

        // fp16 NHWC corner base pointers (512B-aligned)
        const uint4* q00 = (const uint4*)(g_xth + (((size_t)(b * HW + cy0 * W_ + cx0)) << 8));
        const uint4* q01 = (const uint4*)(g_xth + (((size_t)(b * HW + cy0 * W_ + cx1)) << 8));
        const uint4* q10 = (const uint4*)(g_xth + (((size_t)(b * HW + cy1 * W_ + cx0)) << 8));
        const uint4* q11 = (const uint4*)(g_xth + (((size_t)(b * HW + cy1 * W_ + cx1)) << 8));

        // lane covers channels 8*lane .. 8*lane+7
        uint4 a00 = __ldg(q00 + lane);
        uint4 a01 = __ldg(q01 + lane);
        uint4 a10 = __ldg(q10 + lane);
        uint4 a11 = __ldg(q11 + lane);

        float r[8];
#pragma unroll
        for (int m = 0; m < 4; m++) {
            float2 f00 = __half22float2(((const __half2*)&a00)[m]);
            float2 f01 = __half22float2(((const __half2*)&a01)[m]);
            float2 f10 = __half22float2(((const __half2*)&a10)[m]);
            float2 f11 = __half22float2(((const __half2*)&a11)[m]);
            r[2*m+0] = fmaf(w00, f00.x, fmaf(w01, f01.x, fmaf(w10, f10.x, w11 * f11.x)));
            r[2*m+1] = fmaf(w00, f00.y, fmaf(w01, f01.y, fmaf(w10, f10.y, w11 * f11.y)));
        }

        // Permuted-row stores: c = 8*lane + j -> row = j*32 + lane
#pragma unroll
        for (int j = 0; j < 8; j++)
            res_s[(j * 32 + lane) * 33 + px] = r[j];
    }
    __syncthreads();

    // ---- Phase 2: coalesced NCHW write-out ----
    int px2 = tid & 31;           // lanes -> consecutive wr
    int cb  = tid >> 5;           // 0..7
    float* op = out + (((size_t)(b * C_) * HR + hr)) * WR + wr0 + px2;
#pragma unroll
    for (int k = 0; k < 32; k++) {
        int c = cb * 32 + k;
        int row = ((c & 7) << 5) | (c >> 3);
        op[(size_t)c * HWR] = res_s[row * 33 + px2];
    }
}

// ---------------------------------------------------------------------------
extern "C" void kernel_launch(void* const* d_in, const int* in_sizes, int n_in,
                              void* d_out, int out_size)
{
    const float* x      = (const float*)d_in[0];
    const float* weight = (const float*)d_in[1];
    const float* bias   = (const float*)d_in[2];
    float* out          = (float*)d_out;

    // T: NCHW -> NHWC (fp32 + fp16)
    {
        dim3 grid(HW / 32, C_ / 32, B_);
        dim3 block(32, 8);
        dysample_transpose_kernel<<<grid, block>>>(x);
    }

    // A2: offsets -> sampler coords (fp32 NHWC, L2-hot)
    dysample_offset_nhwc_kernel<<<(B_ * H_ * W_) / 8, 256>>>(weight, bias);

    // S3: fp16 NHWC gather + fp32 blend + NCHW write
    {
        dim3 grid(WR / 32, HR, B_);
        dysample_sample_nhwc_kernel<<<grid, 256>>>(out);
    }
}